// round 3
// baseline (speedup 1.0000x reference)
#include <cuda_runtime.h>
#include <cuda_bf16.h>
#include <mma.h>
#include <cstdint>

using namespace nvcuda;

// Problem constants
static constexpr int Bb   = 4;
static constexpr int Sseq = 2048;
static constexpr int Eemb = 1024;
static constexpr int Hh   = 16;
static constexpr int Dd   = 64;
static constexpr int Mrows = Bb * Sseq;   // 8192

// Scratch (device globals: allocation-free)
__device__ float g_q[(size_t)Mrows * Eemb];
__device__ float g_k[(size_t)Mrows * Eemb];
__device__ float g_v[(size_t)Mrows * Eemb];
__device__ float g_o[(size_t)Mrows * Eemb];

// ---------------------------------------------------------------------------
// cp.async helpers
// ---------------------------------------------------------------------------
__device__ __forceinline__ void cp_async16(void* smem, const void* gmem) {
    uint32_t s = (uint32_t)__cvta_generic_to_shared(smem);
    asm volatile("cp.async.cg.shared.global [%0], [%1], 16;\n" :: "r"(s), "l"(gmem));
}
__device__ __forceinline__ void cp_commit() {
    asm volatile("cp.async.commit_group;\n");
}
template<int N> __device__ __forceinline__ void cp_wait() {
    asm volatile("cp.async.wait_group %0;\n" :: "n"(N));
}

// ---------------------------------------------------------------------------
// GEMM: C[M,N] = A[M,K] @ W[K,N] + bias[N]  (M=8192, K=N=1024), tf32 wmma
// 128x128x32 block tile, 256 threads, cp.async double-buffered smem.
// ---------------------------------------------------------------------------
static constexpr int GBM = 128, GBN = 128, GBK = 32;
static constexpr int GEMM_SMEM_BYTES =
    (2 * GBM * GBK + 2 * GBK * GBN + 16 * GBN) * (int)sizeof(float);  // 73728

__global__ __launch_bounds__(256) void gemm_bias_kernel(
    const float* __restrict__ A, const float* __restrict__ W,
    const float* __restrict__ bias, float* __restrict__ C)
{
    constexpr int K = 1024, N = 1024;

    extern __shared__ float smg[];
    float* As    = smg;                                  // [2][GBM*GBK]
    float* Bs    = smg + 2 * GBM * GBK;                  // [2][GBK*GBN]
    float* biasT = smg + 2 * GBM * GBK + 2 * GBK * GBN;  // [16*GBN]

    const int tid  = threadIdx.x;
    const int bm   = blockIdx.y * GBM;
    const int bn   = blockIdx.x * GBN;
    const int warp = tid >> 5;
    const int wr   = warp >> 1;
    const int wc   = warp & 1;

    auto issue_tile = [&](int kt, int buf) {
        const int k0 = kt * GBK;
        float* Ab = As + buf * GBM * GBK;
        float* Bbuf = Bs + buf * GBK * GBN;
        #pragma unroll
        for (int t = 0; t < 4; t++) {
            int lin = tid + t * 256;
            int r = lin >> 3, c4 = lin & 7;
            cp_async16(Ab + r * GBK + c4 * 4,
                       A + (size_t)(bm + r) * K + k0 + c4 * 4);
        }
        #pragma unroll
        for (int t = 0; t < 4; t++) {
            int lin = tid + t * 256;
            int r = lin >> 5, c4 = lin & 31;
            cp_async16(Bbuf + r * GBN + c4 * 4,
                       W + (size_t)(k0 + r) * N + bn + c4 * 4);
        }
    };

    issue_tile(0, 0);
    cp_commit();

    for (int idx = tid; idx < 16 * GBN; idx += 256)
        biasT[idx] = bias[bn + (idx & (GBN - 1))];
    __syncthreads();

    wmma::fragment<wmma::accumulator, 16, 16, 8, float> acc[2][4];
    #pragma unroll
    for (int i = 0; i < 2; i++)
        #pragma unroll
        for (int j = 0; j < 4; j++)
            wmma::load_matrix_sync(acc[i][j], biasT + wc * 64 + j * 16, GBN,
                                   wmma::mem_row_major);

    const int KT = K / GBK;  // 32
    for (int kt = 0; kt < KT; kt++) {
        const int cur = kt & 1;
        if (kt + 1 < KT) {
            issue_tile(kt + 1, cur ^ 1);
            cp_commit();
            cp_wait<1>();
        } else {
            cp_wait<0>();
        }
        __syncthreads();

        const float* Ab = As + cur * GBM * GBK;
        const float* Bbuf = Bs + cur * GBK * GBN;

        #pragma unroll
        for (int kk = 0; kk < GBK; kk += 8) {
            wmma::fragment<wmma::matrix_a, 16, 16, 8, wmma::precision::tf32,
                           wmma::row_major> af[2];
            #pragma unroll
            for (int i = 0; i < 2; i++) {
                wmma::load_matrix_sync(af[i], Ab + (wr * 32 + i * 16) * GBK + kk, GBK);
                #pragma unroll
                for (int t = 0; t < af[i].num_elements; t++)
                    af[i].x[t] = wmma::__float_to_tf32(af[i].x[t]);
            }
            #pragma unroll
            for (int j = 0; j < 4; j++) {
                wmma::fragment<wmma::matrix_b, 16, 16, 8, wmma::precision::tf32,
                               wmma::row_major> bf;
                wmma::load_matrix_sync(bf, Bbuf + kk * GBN + wc * 64 + j * 16, GBN);
                #pragma unroll
                for (int t = 0; t < bf.num_elements; t++)
                    bf.x[t] = wmma::__float_to_tf32(bf.x[t]);
                #pragma unroll
                for (int i = 0; i < 2; i++)
                    wmma::mma_sync(acc[i][j], af[i], bf, acc[i][j]);
            }
        }
        __syncthreads();
    }

    #pragma unroll
    for (int i = 0; i < 2; i++)
        #pragma unroll
        for (int j = 0; j < 4; j++)
            wmma::store_matrix_sync(
                C + (size_t)(bm + wr * 32 + i * 16) * N + bn + wc * 64 + j * 16,
                acc[i][j], N, wmma::mem_row_major);
}

// ---------------------------------------------------------------------------
// Causal flash attention, tf32 wmma, 256 threads, cp.async double-buffered KV.
// Grid: (S/64 q-tiles, B*H). Br=Bc=64, D=64.
// ---------------------------------------------------------------------------
static constexpr int LDP = 72;
static constexpr int TILE_F = 64 * LDP;
// Qs + Ks[2] + Vs[2] + Ss + Ts + Os = 8 tiles, + 3*64 row stats
static constexpr int FLASH_SMEM_BYTES = (8 * TILE_F + 3 * 64) * (int)sizeof(float);

__global__ __launch_bounds__(256) void flash_kernel(
    const float* __restrict__ Q, const float* __restrict__ Kg,
    const float* __restrict__ V, float* __restrict__ O)
{
    extern __shared__ float sm[];
    float* Qs = sm;                       // 64x72
    float* Ks = Qs + TILE_F;              // [2] 64x72
    float* Vs = Ks + 2 * TILE_F;          // [2] 64x72
    float* Ss = Vs + 2 * TILE_F;          // 64x72
    float* Ts = Ss + TILE_F;              // 64x72
    float* Os = Ts + TILE_F;              // 64x72
    float* mrow = Os + TILE_F;
    float* lrow = mrow + 64;
    float* arow = lrow + 64;

    const int tid  = threadIdx.x;
    const int warp = tid >> 5;
    const int wr   = warp >> 1;           // 0..3 : S row block (16 rows)
    const int wc   = warp & 1;            // 0..1 : S col block (32 cols)
    const int qt   = (Sseq / 64 - 1) - blockIdx.x;  // heavy tiles first
    const int bh   = blockIdx.y;
    const int b    = bh >> 4;
    const int h    = bh & 15;
    const float scale = 0.125f;           // 1/sqrt(64)

    const float* qb = Q + ((size_t)b * Sseq + (size_t)qt * 64) * Eemb + h * Dd;
    const float* kb = Kg + (size_t)b * Sseq * Eemb + h * Dd;
    const float* vb = V + (size_t)b * Sseq * Eemb + h * Dd;

    auto issueKV = [&](int j, int buf) {
        const float* kt = kb + (size_t)j * 64 * Eemb;
        const float* vt = vb + (size_t)j * 64 * Eemb;
        float* Kd = Ks + buf * TILE_F;
        float* Vd = Vs + buf * TILE_F;
        #pragma unroll
        for (int t = 0; t < 4; t++) {
            int lin = tid + t * 256;
            int r = lin >> 4, c4 = lin & 15;
            cp_async16(Kd + r * LDP + c4 * 4, kt + (size_t)r * Eemb + c4 * 4);
            cp_async16(Vd + r * LDP + c4 * 4, vt + (size_t)r * Eemb + c4 * 4);
        }
    };

    issueKV(0, 0);
    cp_commit();

    // Q tile, pre-scaled by 1/sqrt(D)
    #pragma unroll
    for (int t = 0; t < 4; t++) {
        int lin = tid + t * 256;
        int r = lin >> 4, c4 = lin & 15;
        float4 v4 = *(const float4*)(qb + (size_t)r * Eemb + c4 * 4);
        v4.x *= scale; v4.y *= scale; v4.z *= scale; v4.w *= scale;
        *(float4*)(Qs + r * LDP + c4 * 4) = v4;
    }
    if (tid < 64) { mrow[tid] = -1e30f; lrow[tid] = 0.f; }
    for (int idx = tid; idx < 64 * 64; idx += 256) {
        int r = idx >> 6, c = idx & 63;
        Os[r * LDP + c] = 0.f;
    }

    for (int j = 0; j <= qt; j++) {
        const int cur = j & 1;
        if (j < qt) {
            issueKV(j + 1, cur ^ 1);
            cp_commit();
            cp_wait<1>();
        } else {
            cp_wait<0>();
        }
        __syncthreads();  // KV[cur] ready (also covers Q/Os/m init at j=0)

        const float* Kc = Ks + cur * TILE_F;
        const float* Vc = Vs + cur * TILE_F;

        // S = (Q*scale) @ K^T : warp computes [wr*16, wc*32] block
        {
            wmma::fragment<wmma::accumulator, 16, 16, 8, float> sacc[2];
            #pragma unroll
            for (int n = 0; n < 2; n++) wmma::fill_fragment(sacc[n], 0.f);
            #pragma unroll
            for (int kk = 0; kk < 64; kk += 8) {
                wmma::fragment<wmma::matrix_a, 16, 16, 8, wmma::precision::tf32,
                               wmma::row_major> af;
                wmma::load_matrix_sync(af, Qs + (wr * 16) * LDP + kk, LDP);
                #pragma unroll
                for (int t = 0; t < af.num_elements; t++)
                    af.x[t] = wmma::__float_to_tf32(af.x[t]);
                #pragma unroll
                for (int n = 0; n < 2; n++) {
                    wmma::fragment<wmma::matrix_b, 16, 16, 8, wmma::precision::tf32,
                                   wmma::col_major> bf;
                    wmma::load_matrix_sync(bf, Kc + (wc * 32 + n * 16) * LDP + kk, LDP);
                    #pragma unroll
                    for (int t = 0; t < bf.num_elements; t++)
                        bf.x[t] = wmma::__float_to_tf32(bf.x[t]);
                    wmma::mma_sync(sacc[n], af, bf, sacc[n]);
                }
            }
            #pragma unroll
            for (int n = 0; n < 2; n++)
                wmma::store_matrix_sync(Ss + (wr * 16) * LDP + wc * 32 + n * 16,
                                        sacc[n], LDP, wmma::mem_row_major);
        }
        __syncthreads();

        // Online softmax: 4 threads per row, 16 cols each; causal mask fused.
        {
            const int r    = tid >> 2;
            const int q4   = tid & 3;
            const int base = q4 * 16;
            float* srow = Ss + r * LDP + base;
            const bool diag = (j == qt);

            float lm = -1e30f;
            #pragma unroll
            for (int c = 0; c < 16; c++) {
                float s = srow[c];
                bool ok = !diag || (base + c <= r);
                if (ok) lm = fmaxf(lm, s);
            }
            lm = fmaxf(lm, __shfl_xor_sync(0xffffffffu, lm, 1));
            lm = fmaxf(lm, __shfl_xor_sync(0xffffffffu, lm, 2));
            const float mo = mrow[r];
            const float mx = fmaxf(mo, lm);

            float sum = 0.f;
            #pragma unroll
            for (int c = 0; c < 16; c++) {
                float s = srow[c];
                bool ok = !diag || (base + c <= r);
                float p = ok ? __expf(s - mx) : 0.f;
                srow[c] = p;
                sum += p;
            }
            sum += __shfl_xor_sync(0xffffffffu, sum, 1);
            sum += __shfl_xor_sync(0xffffffffu, sum, 2);

            if (q4 == 0) {
                float al = __expf(mo - mx);
                mrow[r] = mx;
                lrow[r] = lrow[r] * al + sum;
                arow[r] = al;
            }
        }
        __syncthreads();

        // T = P @ V : warp computes [wr*16, wc*32] block
        {
            wmma::fragment<wmma::accumulator, 16, 16, 8, float> tacc[2];
            #pragma unroll
            for (int n = 0; n < 2; n++) wmma::fill_fragment(tacc[n], 0.f);
            #pragma unroll
            for (int kk = 0; kk < 64; kk += 8) {
                wmma::fragment<wmma::matrix_a, 16, 16, 8, wmma::precision::tf32,
                               wmma::row_major> af;
                wmma::load_matrix_sync(af, Ss + (wr * 16) * LDP + kk, LDP);
                #pragma unroll
                for (int t = 0; t < af.num_elements; t++)
                    af.x[t] = wmma::__float_to_tf32(af.x[t]);
                #pragma unroll
                for (int n = 0; n < 2; n++) {
                    wmma::fragment<wmma::matrix_b, 16, 16, 8, wmma::precision::tf32,
                                   wmma::row_major> bf;
                    wmma::load_matrix_sync(bf, Vc + kk * LDP + wc * 32 + n * 16, LDP);
                    #pragma unroll
                    for (int t = 0; t < bf.num_elements; t++)
                        bf.x[t] = wmma::__float_to_tf32(bf.x[t]);
                    wmma::mma_sync(tacc[n], af, bf, tacc[n]);
                }
            }
            #pragma unroll
            for (int n = 0; n < 2; n++)
                wmma::store_matrix_sync(Ts + (wr * 16) * LDP + wc * 32 + n * 16,
                                        tacc[n], LDP, wmma::mem_row_major);
        }
        __syncthreads();

        // O = O*alpha + T
        for (int idx = tid; idx < 64 * 64; idx += 256) {
            int r = idx >> 6, c = idx & 63;
            Os[r * LDP + c] = Os[r * LDP + c] * arow[r] + Ts[r * LDP + c];
        }
        // no loop-end sync: the next iteration's top sync orders Ss rewrite
    }

    // epilogue (same thread->element mapping as the O update, no sync needed)
    float* ob = O + ((size_t)b * Sseq + (size_t)qt * 64) * Eemb + h * Dd;
    for (int idx = tid; idx < 64 * 64; idx += 256) {
        int r = idx >> 6, c = idx & 63;
        ob[(size_t)r * Eemb + c] = Os[r * LDP + c] / lrow[r];
    }
}

// ---------------------------------------------------------------------------
extern "C" void kernel_launch(void* const* d_in, const int* in_sizes, int n_in,
                              void* d_out, int out_size)
{
    const float* q   = (const float*)d_in[0];
    const float* k   = (const float*)d_in[1];
    const float* v   = (const float*)d_in[2];
    const float* w_q = (const float*)d_in[3];
    const float* b_q = (const float*)d_in[4];
    const float* w_k = (const float*)d_in[5];
    const float* b_k = (const float*)d_in[6];
    const float* w_v = (const float*)d_in[7];
    const float* b_v = (const float*)d_in[8];
    const float* w_o = (const float*)d_in[9];
    const float* b_o = (const float*)d_in[10];
    float* out = (float*)d_out;

    float *gq, *gk, *gv, *go;
    cudaGetSymbolAddress((void**)&gq, g_q);
    cudaGetSymbolAddress((void**)&gk, g_k);
    cudaGetSymbolAddress((void**)&gv, g_v);
    cudaGetSymbolAddress((void**)&go, g_o);

    cudaFuncSetAttribute(gemm_bias_kernel,
                         cudaFuncAttributeMaxDynamicSharedMemorySize,
                         GEMM_SMEM_BYTES);
    cudaFuncSetAttribute(flash_kernel,
                         cudaFuncAttributeMaxDynamicSharedMemorySize,
                         FLASH_SMEM_BYTES);

    dim3 gGrid(Eemb / 128, Mrows / 128);   // (8, 64)
    gemm_bias_kernel<<<gGrid, 256, GEMM_SMEM_BYTES>>>(q, w_q, b_q, gq);
    gemm_bias_kernel<<<gGrid, 256, GEMM_SMEM_BYTES>>>(k, w_k, b_k, gk);
    gemm_bias_kernel<<<gGrid, 256, GEMM_SMEM_BYTES>>>(v, w_v, b_v, gv);

    dim3 fGrid(Sseq / 64, Bb * Hh);        // (32, 64)
    flash_kernel<<<fGrid, 256, FLASH_SMEM_BYTES>>>(gq, gk, gv, go);

    gemm_bias_kernel<<<gGrid, 256, GEMM_SMEM_BYTES>>>(go, w_o, b_o, out);
}

// round 6
// speedup vs baseline: 1.1414x; 1.1414x over previous
#include <cuda_runtime.h>
#include <cuda_bf16.h>
#include <mma.h>
#include <cstdint>

using namespace nvcuda;

// Problem constants
static constexpr int Bb   = 4;
static constexpr int Sseq = 2048;
static constexpr int Eemb = 1024;
static constexpr int Hh   = 16;
static constexpr int Dd   = 64;
static constexpr int Mrows = Bb * Sseq;   // 8192

// Scratch (device globals: allocation-free)
__device__ float g_q[(size_t)Mrows * Eemb];
__device__ float g_k[(size_t)Mrows * Eemb];
__device__ float g_v[(size_t)Mrows * Eemb];
__device__ float g_o[(size_t)Mrows * Eemb];

// ---------------------------------------------------------------------------
// cp.async helpers
// ---------------------------------------------------------------------------
__device__ __forceinline__ void cp_async16(void* smem, const void* gmem) {
    uint32_t s = (uint32_t)__cvta_generic_to_shared(smem);
    asm volatile("cp.async.cg.shared.global [%0], [%1], 16;\n" :: "r"(s), "l"(gmem));
}
__device__ __forceinline__ void cp_commit() {
    asm volatile("cp.async.commit_group;\n");
}
template<int N> __device__ __forceinline__ void cp_wait() {
    asm volatile("cp.async.wait_group %0;\n" :: "n"(N));
}

// ---------------------------------------------------------------------------
// GEMM: C[M,N] = A[M,K] @ W[K,N] + bias[N]  (M=8192, K=N=1024), tf32 wmma
// 128x128x32 block tile, 256 threads, cp.async double-buffered smem.
// ---------------------------------------------------------------------------
static constexpr int GBM = 128, GBN = 128, GBK = 32;
static constexpr int GEMM_SMEM_BYTES =
    (2 * GBM * GBK + 2 * GBK * GBN + 16 * GBN) * (int)sizeof(float);  // 73728

__global__ __launch_bounds__(256) void gemm_bias_kernel(
    const float* __restrict__ A, const float* __restrict__ W,
    const float* __restrict__ bias, float* __restrict__ C)
{
    constexpr int K = 1024, N = 1024;

    extern __shared__ float smg[];
    float* As    = smg;                                  // [2][GBM*GBK]
    float* Bs    = smg + 2 * GBM * GBK;                  // [2][GBK*GBN]
    float* biasT = smg + 2 * GBM * GBK + 2 * GBK * GBN;  // [16*GBN]

    const int tid  = threadIdx.x;
    const int bm   = blockIdx.y * GBM;
    const int bn   = blockIdx.x * GBN;
    const int warp = tid >> 5;
    const int wr   = warp >> 1;
    const int wc   = warp & 1;

    auto issue_tile = [&](int kt, int buf) {
        const int k0 = kt * GBK;
        float* Ab = As + buf * GBM * GBK;
        float* Bbuf = Bs + buf * GBK * GBN;
        #pragma unroll
        for (int t = 0; t < 4; t++) {
            int lin = tid + t * 256;
            int r = lin >> 3, c4 = lin & 7;
            cp_async16(Ab + r * GBK + c4 * 4,
                       A + (size_t)(bm + r) * K + k0 + c4 * 4);
        }
        #pragma unroll
        for (int t = 0; t < 4; t++) {
            int lin = tid + t * 256;
            int r = lin >> 5, c4 = lin & 31;
            cp_async16(Bbuf + r * GBN + c4 * 4,
                       W + (size_t)(k0 + r) * N + bn + c4 * 4);
        }
    };

    issue_tile(0, 0);
    cp_commit();

    for (int idx = tid; idx < 16 * GBN; idx += 256)
        biasT[idx] = bias[bn + (idx & (GBN - 1))];
    __syncthreads();

    wmma::fragment<wmma::accumulator, 16, 16, 8, float> acc[2][4];
    #pragma unroll
    for (int i = 0; i < 2; i++)
        #pragma unroll
        for (int j = 0; j < 4; j++)
            wmma::load_matrix_sync(acc[i][j], biasT + wc * 64 + j * 16, GBN,
                                   wmma::mem_row_major);

    const int KT = K / GBK;  // 32
    for (int kt = 0; kt < KT; kt++) {
        const int cur = kt & 1;
        // wait for KV[cur]'s group, make visible, then prefetch next tile.
        cp_wait<0>();
        __syncthreads();
        if (kt + 1 < KT) {
            issue_tile(kt + 1, cur ^ 1);
            cp_commit();
        }

        const float* Ab = As + cur * GBM * GBK;
        const float* Bbuf = Bs + cur * GBK * GBN;

        #pragma unroll
        for (int kk = 0; kk < GBK; kk += 8) {
            wmma::fragment<wmma::matrix_a, 16, 16, 8, wmma::precision::tf32,
                           wmma::row_major> af[2];
            #pragma unroll
            for (int i = 0; i < 2; i++) {
                wmma::load_matrix_sync(af[i], Ab + (wr * 32 + i * 16) * GBK + kk, GBK);
                #pragma unroll
                for (int t = 0; t < af[i].num_elements; t++)
                    af[i].x[t] = wmma::__float_to_tf32(af[i].x[t]);
            }
            #pragma unroll
            for (int j = 0; j < 4; j++) {
                wmma::fragment<wmma::matrix_b, 16, 16, 8, wmma::precision::tf32,
                               wmma::row_major> bf;
                wmma::load_matrix_sync(bf, Bbuf + kk * GBN + wc * 64 + j * 16, GBN);
                #pragma unroll
                for (int t = 0; t < bf.num_elements; t++)
                    bf.x[t] = wmma::__float_to_tf32(bf.x[t]);
                #pragma unroll
                for (int i = 0; i < 2; i++)
                    wmma::mma_sync(acc[i][j], af[i], bf, acc[i][j]);
            }
        }
        // no end sync needed: next iteration's __syncthreads (after cp_wait)
        // orders the buffer overwrite after all reads of it.
    }

    #pragma unroll
    for (int i = 0; i < 2; i++)
        #pragma unroll
        for (int j = 0; j < 4; j++)
            wmma::store_matrix_sync(
                C + (size_t)(bm + wr * 32 + i * 16) * N + bn + wc * 64 + j * 16,
                acc[i][j], N, wmma::mem_row_major);
}

// ---------------------------------------------------------------------------
// Causal flash attention, tf32 wmma, 256 threads, cp.async double-buffered KV.
// Register-resident O accumulators; per-row rescale via accumulator-shaped
// "alpha fragments" (identical fragment type => identical lane mapping).
// Pipeline order per iteration: wait -> sync(S1) -> prefetch-next -> compute,
// so the prefetch write is provably ordered after all readers of that buffer.
// smem = 109,056 B -> 2 CTAs/SM.
// ---------------------------------------------------------------------------
static constexpr int LDP = 68;
static constexpr int TILE_F = 64 * LDP;
static constexpr int FLASH_SMEM_BYTES =
    (6 * TILE_F + 64 * 16 + 2 * 64) * (int)sizeof(float);  // 109056

__global__ __launch_bounds__(256) void flash_kernel(
    const float* __restrict__ Q, const float* __restrict__ Kg,
    const float* __restrict__ V, float* __restrict__ O)
{
    extern __shared__ float sm[];
    float* Qs      = sm;                   // 64x68
    float* Ks      = Qs + TILE_F;          // [2] 64x68
    float* Vs      = Ks + 2 * TILE_F;      // [2] 64x68
    float* Ss      = Vs + 2 * TILE_F;      // 64x68
    float* alpha_s = Ss + TILE_F;          // 64x16
    float* mrow    = alpha_s + 64 * 16;    // [64]
    float* lrow    = mrow + 64;            // [64]

    const int tid  = threadIdx.x;
    const int warp = tid >> 5;
    const int wr   = warp >> 1;            // 0..3 : 16-row block
    const int wc   = warp & 1;             // 0..1 : 32-col block
    const int qt   = (Sseq / 64 - 1) - blockIdx.x;  // heavy tiles first
    const int bh   = blockIdx.y;
    const int b    = bh >> 4;
    const int h    = bh & 15;
    const float scale = 0.125f;            // 1/sqrt(64)

    const float* qb = Q + ((size_t)b * Sseq + (size_t)qt * 64) * Eemb + h * Dd;
    const float* kb = Kg + (size_t)b * Sseq * Eemb + h * Dd;
    const float* vb = V + (size_t)b * Sseq * Eemb + h * Dd;

    auto issueKV = [&](int j, int buf) {
        const float* kt = kb + (size_t)j * 64 * Eemb;
        const float* vt = vb + (size_t)j * 64 * Eemb;
        float* Kd = Ks + buf * TILE_F;
        float* Vd = Vs + buf * TILE_F;
        #pragma unroll
        for (int t = 0; t < 4; t++) {
            int lin = tid + t * 256;
            int r = lin >> 4, c4 = lin & 15;
            cp_async16(Kd + r * LDP + c4 * 4, kt + (size_t)r * Eemb + c4 * 4);
            cp_async16(Vd + r * LDP + c4 * 4, vt + (size_t)r * Eemb + c4 * 4);
        }
    };

    issueKV(0, 0);
    cp_commit();

    // Q tile, pre-scaled by 1/sqrt(D)
    #pragma unroll
    for (int t = 0; t < 4; t++) {
        int lin = tid + t * 256;
        int r = lin >> 4, c4 = lin & 15;
        float4 v4 = *(const float4*)(qb + (size_t)r * Eemb + c4 * 4);
        v4.x *= scale; v4.y *= scale; v4.z *= scale; v4.w *= scale;
        *(float4*)(Qs + r * LDP + c4 * 4) = v4;
    }
    if (tid < 64) { mrow[tid] = -1e30f; lrow[tid] = 0.f; }

    // persistent O accumulators: warp's 16x32 block
    wmma::fragment<wmma::accumulator, 16, 16, 8, float> oacc[2];
    #pragma unroll
    for (int n = 0; n < 2; n++) wmma::fill_fragment(oacc[n], 0.f);

    for (int j = 0; j <= qt; j++) {
        const int cur = j & 1;

        cp_wait<0>();
        __syncthreads();  // S1: KV[cur] visible to ALL warps; every warp has
                          // finished iteration j-1 (so buffer cur^1 is free).
        if (j < qt) {
            issueKV(j + 1, cur ^ 1);
            cp_commit();
        }

        const float* Kc = Ks + cur * TILE_F;
        const float* Vc = Vs + cur * TILE_F;

        // S = (Q*scale) @ K^T : warp computes [wr*16, wc*32] block
        {
            wmma::fragment<wmma::accumulator, 16, 16, 8, float> sacc[2];
            #pragma unroll
            for (int n = 0; n < 2; n++) wmma::fill_fragment(sacc[n], 0.f);
            #pragma unroll
            for (int kk = 0; kk < 64; kk += 8) {
                wmma::fragment<wmma::matrix_a, 16, 16, 8, wmma::precision::tf32,
                               wmma::row_major> af;
                wmma::load_matrix_sync(af, Qs + (wr * 16) * LDP + kk, LDP);
                #pragma unroll
                for (int t = 0; t < af.num_elements; t++)
                    af.x[t] = wmma::__float_to_tf32(af.x[t]);
                #pragma unroll
                for (int n = 0; n < 2; n++) {
                    wmma::fragment<wmma::matrix_b, 16, 16, 8, wmma::precision::tf32,
                                   wmma::col_major> bf;
                    wmma::load_matrix_sync(bf, Kc + (wc * 32 + n * 16) * LDP + kk, LDP);
                    #pragma unroll
                    for (int t = 0; t < bf.num_elements; t++)
                        bf.x[t] = wmma::__float_to_tf32(bf.x[t]);
                    wmma::mma_sync(sacc[n], af, bf, sacc[n]);
                }
            }
            #pragma unroll
            for (int n = 0; n < 2; n++)
                wmma::store_matrix_sync(Ss + (wr * 16) * LDP + wc * 32 + n * 16,
                                        sacc[n], LDP, wmma::mem_row_major);
        }
        __syncthreads();  // S2: full S tile visible

        // Online softmax: 4 threads per row, 16 cols each; causal mask fused.
        // Also builds the alpha tile (64x16, every col = alpha[row]).
        {
            const int r    = tid >> 2;
            const int q4   = tid & 3;
            const int base = q4 * 16;
            float* srow = Ss + r * LDP + base;
            const bool diag = (j == qt);

            float lm = -1e30f;
            #pragma unroll
            for (int c = 0; c < 16; c++) {
                float s = srow[c];
                bool ok = !diag || (base + c <= r);
                if (ok) lm = fmaxf(lm, s);
            }
            lm = fmaxf(lm, __shfl_xor_sync(0xffffffffu, lm, 1));
            lm = fmaxf(lm, __shfl_xor_sync(0xffffffffu, lm, 2));
            const float mo = mrow[r];
            const float mx = fmaxf(mo, lm);

            float sum = 0.f;
            #pragma unroll
            for (int c = 0; c < 16; c++) {
                float s = srow[c];
                bool ok = !diag || (base + c <= r);
                float p = ok ? __expf(s - mx) : 0.f;
                srow[c] = p;
                sum += p;
            }
            sum += __shfl_xor_sync(0xffffffffu, sum, 1);
            sum += __shfl_xor_sync(0xffffffffu, sum, 2);

            const float al = __expf(mo - mx);
            #pragma unroll
            for (int i = 0; i < 4; i++)
                alpha_s[r * 16 + q4 * 4 + i] = al;

            if (q4 == 0) {
                mrow[r] = mx;
                lrow[r] = lrow[r] * al + sum;
            }
        }
        __syncthreads();  // S3: P and alpha tile visible

        // T = P @ V ; O = alpha*O + T   (all in registers)
        {
            wmma::fragment<wmma::accumulator, 16, 16, 8, float> alphaF;
            wmma::load_matrix_sync(alphaF, alpha_s + (wr * 16) * 16, 16,
                                   wmma::mem_row_major);

            wmma::fragment<wmma::accumulator, 16, 16, 8, float> tacc[2];
            #pragma unroll
            for (int n = 0; n < 2; n++) wmma::fill_fragment(tacc[n], 0.f);
            #pragma unroll
            for (int kk = 0; kk < 64; kk += 8) {
                wmma::fragment<wmma::matrix_a, 16, 16, 8, wmma::precision::tf32,
                               wmma::row_major> af;
                wmma::load_matrix_sync(af, Ss + (wr * 16) * LDP + kk, LDP);
                #pragma unroll
                for (int t = 0; t < af.num_elements; t++)
                    af.x[t] = wmma::__float_to_tf32(af.x[t]);
                #pragma unroll
                for (int n = 0; n < 2; n++) {
                    wmma::fragment<wmma::matrix_b, 16, 16, 8, wmma::precision::tf32,
                                   wmma::row_major> bf;
                    wmma::load_matrix_sync(bf, Vc + kk * LDP + wc * 32 + n * 16, LDP);
                    #pragma unroll
                    for (int t = 0; t < bf.num_elements; t++)
                        bf.x[t] = wmma::__float_to_tf32(bf.x[t]);
                    wmma::mma_sync(tacc[n], af, bf, tacc[n]);
                }
            }
            #pragma unroll
            for (int n = 0; n < 2; n++)
                #pragma unroll
                for (int t = 0; t < oacc[n].num_elements; t++)
                    oacc[n].x[t] = oacc[n].x[t] * alphaF.x[t] + tacc[n].x[t];
        }
        // loop back: S1 of next iteration orders all buffer rewrites
    }

    // epilogue: O *= 1/l (via reciprocal fragment), store direct to gmem
    __syncthreads();  // all warps done reading alpha_s / writing lrow
    {
        const int r  = tid >> 2;
        const int q4 = tid & 3;
        const float rl = 1.f / lrow[r];
        #pragma unroll
        for (int i = 0; i < 4; i++)
            alpha_s[r * 16 + q4 * 4 + i] = rl;
    }
    __syncthreads();
    {
        wmma::fragment<wmma::accumulator, 16, 16, 8, float> recipF;
        wmma::load_matrix_sync(recipF, alpha_s + (wr * 16) * 16, 16,
                               wmma::mem_row_major);
        float* ob = O + ((size_t)b * Sseq + (size_t)qt * 64 + wr * 16) * Eemb
                      + h * Dd + wc * 32;
        #pragma unroll
        for (int n = 0; n < 2; n++) {
            #pragma unroll
            for (int t = 0; t < oacc[n].num_elements; t++)
                oacc[n].x[t] *= recipF.x[t];
            wmma::store_matrix_sync(ob + n * 16, oacc[n], Eemb,
                                    wmma::mem_row_major);
        }
    }
}

// ---------------------------------------------------------------------------
extern "C" void kernel_launch(void* const* d_in, const int* in_sizes, int n_in,
                              void* d_out, int out_size)
{
    const float* q   = (const float*)d_in[0];
    const float* k   = (const float*)d_in[1];
    const float* v   = (const float*)d_in[2];
    const float* w_q = (const float*)d_in[3];
    const float* b_q = (const float*)d_in[4];
    const float* w_k = (const float*)d_in[5];
    const float* b_k = (const float*)d_in[6];
    const float* w_v = (const float*)d_in[7];
    const float* b_v = (const float*)d_in[8];
    const float* w_o = (const float*)d_in[9];
    const float* b_o = (const float*)d_in[10];
    float* out = (float*)d_out;

    float *gq, *gk, *gv, *go;
    cudaGetSymbolAddress((void**)&gq, g_q);
    cudaGetSymbolAddress((void**)&gk, g_k);
    cudaGetSymbolAddress((void**)&gv, g_v);
    cudaGetSymbolAddress((void**)&go, g_o);

    cudaFuncSetAttribute(gemm_bias_kernel,
                         cudaFuncAttributeMaxDynamicSharedMemorySize,
                         GEMM_SMEM_BYTES);
    cudaFuncSetAttribute(flash_kernel,
                         cudaFuncAttributeMaxDynamicSharedMemorySize,
                         FLASH_SMEM_BYTES);

    dim3 gGrid(Eemb / 128, Mrows / 128);   // (8, 64)
    gemm_bias_kernel<<<gGrid, 256, GEMM_SMEM_BYTES>>>(q, w_q, b_q, gq);
    gemm_bias_kernel<<<gGrid, 256, GEMM_SMEM_BYTES>>>(k, w_k, b_k, gk);
    gemm_bias_kernel<<<gGrid, 256, GEMM_SMEM_BYTES>>>(v, w_v, b_v, gv);

    dim3 fGrid(Sseq / 64, Bb * Hh);        // (32, 64)
    flash_kernel<<<fGrid, 256, FLASH_SMEM_BYTES>>>(gq, gk, gv, go);

    gemm_bias_kernel<<<gGrid, 256, GEMM_SMEM_BYTES>>>(go, w_o, b_o, out);
}

// round 7
// speedup vs baseline: 1.4265x; 1.2497x over previous
#include <cuda_runtime.h>
#include <cuda_bf16.h>
#include <mma.h>
#include <cstdint>

using namespace nvcuda;

// Problem constants
static constexpr int Bb   = 4;
static constexpr int Sseq = 2048;
static constexpr int Eemb = 1024;
static constexpr int Hh   = 16;
static constexpr int Dd   = 64;
static constexpr int Mrows = Bb * Sseq;   // 8192

// Scratch (device globals: allocation-free)
__device__ float g_q[(size_t)Mrows * Eemb];
__device__ float g_k[(size_t)Mrows * Eemb];
__device__ float g_v[(size_t)Mrows * Eemb];
__device__ float g_o[(size_t)Mrows * Eemb];

// ---------------------------------------------------------------------------
// cp.async helpers
// ---------------------------------------------------------------------------
__device__ __forceinline__ void cp_async16(void* smem, const void* gmem) {
    uint32_t s = (uint32_t)__cvta_generic_to_shared(smem);
    asm volatile("cp.async.cg.shared.global [%0], [%1], 16;\n" :: "r"(s), "l"(gmem));
}
__device__ __forceinline__ void cp_commit() {
    asm volatile("cp.async.commit_group;\n");
}
template<int N> __device__ __forceinline__ void cp_wait() {
    asm volatile("cp.async.wait_group %0;\n" :: "n"(N));
}

// ---------------------------------------------------------------------------
// GEMM: C[M,N] = A[M,K] @ W[K,N] + bias[N]  (M=8192, K=N=1024), tf32 wmma
// 128x128x32 tile, 256 threads, cp.async double buffer.
// Padded smem strides (LDA=36, LDB=132) kill the 8-way bank conflicts of the
// previous 32/128 strides. Bias added in the epilogue per accumulator element
// (standard m16n8 layout: col = (lane&3)*2 + (t&1) + ((t&4)?8:0)).
// smem = 69 KB -> 3 CTAs/SM.
// ---------------------------------------------------------------------------
static constexpr int GBM = 128, GBN = 128, GBK = 32;
static constexpr int LDA = 36;    // GBK + 4
static constexpr int LDB = 132;   // GBN + 4
static constexpr int GEMM_SMEM_BYTES =
    (2 * GBM * LDA + 2 * GBK * LDB) * (int)sizeof(float);  // 70656

__global__ __launch_bounds__(256) void gemm_bias_kernel(
    const float* __restrict__ A, const float* __restrict__ W,
    const float* __restrict__ bias, float* __restrict__ C)
{
    constexpr int K = 1024, N = 1024;

    extern __shared__ float smg[];
    float* As = smg;                   // [2][GBM*LDA]
    float* Bs = smg + 2 * GBM * LDA;   // [2][GBK*LDB]

    const int tid  = threadIdx.x;
    const int lane = tid & 31;
    const int bm   = blockIdx.y * GBM;
    const int bn   = blockIdx.x * GBN;
    const int warp = tid >> 5;
    const int wr   = warp >> 1;
    const int wc   = warp & 1;

    auto issue_tile = [&](int kt, int buf) {
        const int k0 = kt * GBK;
        float* Ab = As + buf * GBM * LDA;
        float* Bbuf = Bs + buf * GBK * LDB;
        #pragma unroll
        for (int t = 0; t < 4; t++) {
            int lin = tid + t * 256;
            int r = lin >> 3, c4 = lin & 7;
            cp_async16(Ab + r * LDA + c4 * 4,
                       A + (size_t)(bm + r) * K + k0 + c4 * 4);
        }
        #pragma unroll
        for (int t = 0; t < 4; t++) {
            int lin = tid + t * 256;
            int r = lin >> 5, c4 = lin & 31;
            cp_async16(Bbuf + r * LDB + c4 * 4,
                       W + (size_t)(k0 + r) * N + bn + c4 * 4);
        }
    };

    issue_tile(0, 0);
    cp_commit();

    wmma::fragment<wmma::accumulator, 16, 16, 8, float> acc[2][4];
    #pragma unroll
    for (int i = 0; i < 2; i++)
        #pragma unroll
        for (int j = 0; j < 4; j++)
            wmma::fill_fragment(acc[i][j], 0.f);

    const int KT = K / GBK;  // 32
    for (int kt = 0; kt < KT; kt++) {
        const int cur = kt & 1;
        cp_wait<0>();
        __syncthreads();
        if (kt + 1 < KT) {
            issue_tile(kt + 1, cur ^ 1);
            cp_commit();
        }

        const float* Ab = As + cur * GBM * LDA;
        const float* Bbuf = Bs + cur * GBK * LDB;

        #pragma unroll
        for (int kk = 0; kk < GBK; kk += 8) {
            wmma::fragment<wmma::matrix_a, 16, 16, 8, wmma::precision::tf32,
                           wmma::row_major> af[2];
            #pragma unroll
            for (int i = 0; i < 2; i++) {
                wmma::load_matrix_sync(af[i], Ab + (wr * 32 + i * 16) * LDA + kk, LDA);
                #pragma unroll
                for (int t = 0; t < af[i].num_elements; t++)
                    af[i].x[t] = wmma::__float_to_tf32(af[i].x[t]);
            }
            #pragma unroll
            for (int j = 0; j < 4; j++) {
                wmma::fragment<wmma::matrix_b, 16, 16, 8, wmma::precision::tf32,
                               wmma::row_major> bf;
                wmma::load_matrix_sync(bf, Bbuf + kk * LDB + wc * 64 + j * 16, LDB);
                #pragma unroll
                for (int t = 0; t < bf.num_elements; t++)
                    bf.x[t] = wmma::__float_to_tf32(bf.x[t]);
                #pragma unroll
                for (int i = 0; i < 2; i++)
                    wmma::mma_sync(acc[i][j], af[i], bf, acc[i][j]);
            }
        }
    }

    // epilogue: add bias per element (col from standard acc layout), store
    #pragma unroll
    for (int j = 0; j < 4; j++) {
        const int col0 = bn + wc * 64 + j * 16 + (lane & 3) * 2;
        float b0 = __ldg(bias + col0);
        float b1 = __ldg(bias + col0 + 1);
        float b8 = __ldg(bias + col0 + 8);
        float b9 = __ldg(bias + col0 + 9);
        #pragma unroll
        for (int i = 0; i < 2; i++) {
            acc[i][j].x[0] += b0; acc[i][j].x[1] += b1;
            acc[i][j].x[2] += b0; acc[i][j].x[3] += b1;
            acc[i][j].x[4] += b8; acc[i][j].x[5] += b9;
            acc[i][j].x[6] += b8; acc[i][j].x[7] += b9;
            wmma::store_matrix_sync(
                C + (size_t)(bm + wr * 32 + i * 16) * N + bn + wc * 64 + j * 16,
                acc[i][j], N, wmma::mem_row_major);
        }
    }
}

// ---------------------------------------------------------------------------
// Causal flash attention, tf32 wmma, Br=128, Bc=64, 8 warps.
// Warp w owns rows [16w,16w+16) of the 128-row Q tile, all 64 cols.
// Softmax fully in registers (standard m16n8 acc layout:
//   rows: elems {0,1,4,5} -> lane>>2, {2,3,6,7} -> lane>>2 + 8
//   cols: (lane&3)*2 + (t&1) + ((t&4)?8:0) + 16n ),
// m/l/alpha in registers, P stored to smem once as the PV A-operand.
// 2 syncs/iter. smem = 136 KB -> 1 CTA/SM.
// ---------------------------------------------------------------------------
static constexpr int LDP = 68;
static constexpr int KVTILE = 64 * LDP;        // 64x68
static constexpr int QTILE  = 128 * LDP;       // 128x68
static constexpr int FLASH_SMEM_BYTES =
    (QTILE + 4 * KVTILE + QTILE) * (int)sizeof(float);   // 139264

__global__ __launch_bounds__(256, 1) void flash_kernel(
    const float* __restrict__ Q, const float* __restrict__ Kg,
    const float* __restrict__ V, float* __restrict__ O)
{
    extern __shared__ float sm[];
    float* Qs = sm;                    // 128x68
    float* Ks = Qs + QTILE;            // [2] 64x68
    float* Vs = Ks + 2 * KVTILE;       // [2] 64x68
    float* Ps = Vs + 2 * KVTILE;       // 128x68

    const int tid  = threadIdx.x;
    const int warp = tid >> 5;         // 0..7 -> rows 16w..16w+15
    const int lane = tid & 31;
    const int qt   = (Sseq / 128 - 1) - blockIdx.x;  // heavy tiles first
    const int bh   = blockIdx.y;
    const int b    = bh >> 4;
    const int h    = bh & 15;
    const float scale = 0.125f;        // 1/sqrt(64)

    const float* qb = Q + ((size_t)b * Sseq + (size_t)qt * 128) * Eemb + h * Dd;
    const float* kb = Kg + (size_t)b * Sseq * Eemb + h * Dd;
    const float* vb = V + (size_t)b * Sseq * Eemb + h * Dd;

    auto issueKV = [&](int j, int buf) {
        const float* kt = kb + (size_t)j * 64 * Eemb;
        const float* vt = vb + (size_t)j * 64 * Eemb;
        float* Kd = Ks + buf * KVTILE;
        float* Vd = Vs + buf * KVTILE;
        #pragma unroll
        for (int t = 0; t < 4; t++) {
            int lin = tid + t * 256;
            int r = lin >> 4, c4 = lin & 15;
            cp_async16(Kd + r * LDP + c4 * 4, kt + (size_t)r * Eemb + c4 * 4);
            cp_async16(Vd + r * LDP + c4 * 4, vt + (size_t)r * Eemb + c4 * 4);
        }
    };

    issueKV(0, 0);
    cp_commit();

    // Q tile (128 rows), pre-scaled
    #pragma unroll
    for (int t = 0; t < 8; t++) {
        int lin = tid + t * 256;
        int r = lin >> 4, c4 = lin & 15;
        float4 v4 = *(const float4*)(qb + (size_t)r * Eemb + c4 * 4);
        v4.x *= scale; v4.y *= scale; v4.z *= scale; v4.w *= scale;
        *(float4*)(Qs + r * LDP + c4 * 4) = v4;
    }

    // register stats for this thread's two rows (lane>>2, lane>>2+8)
    float m0 = -1e30f, m1 = -1e30f, l0 = 0.f, l1 = 0.f;

    wmma::fragment<wmma::accumulator, 16, 16, 8, float> oacc[4];
    #pragma unroll
    for (int n = 0; n < 4; n++) wmma::fill_fragment(oacc[n], 0.f);

    const int nkv = 2 * qt + 2;  // KV 64-row tiles covering keys <= last row
    const int warp_row0 = warp * 16;            // local row base
    const int lr0 = warp_row0 + (lane >> 2);    // this thread's local rows
    const int lr1 = lr0 + 8;

    for (int j = 0; j < nkv; j++) {
        const int cur = j & 1;

        cp_wait<0>();
        __syncthreads();  // S1: KV[cur] visible, Ps/KV[cur^1] free
        if (j + 1 < nkv) {
            issueKV(j + 1, cur ^ 1);
            cp_commit();
        }

        const float* Kc = Ks + cur * KVTILE;
        const float* Vc = Vs + cur * KVTILE;

        // keys in this tile start at 64*j; warp active unless all its rows < first key
        const int off = 64 * j - 128 * qt;        // col+off > lr  => masked
        const bool active = (64 * j <= 128 * qt + warp_row0 + 15);

        if (active) {
            // S = Q @ K^T (16x64 per warp)
            wmma::fragment<wmma::accumulator, 16, 16, 8, float> sacc[4];
            #pragma unroll
            for (int n = 0; n < 4; n++) wmma::fill_fragment(sacc[n], 0.f);
            #pragma unroll
            for (int kk = 0; kk < 64; kk += 8) {
                wmma::fragment<wmma::matrix_a, 16, 16, 8, wmma::precision::tf32,
                               wmma::row_major> af;
                wmma::load_matrix_sync(af, Qs + warp_row0 * LDP + kk, LDP);
                #pragma unroll
                for (int t = 0; t < af.num_elements; t++)
                    af.x[t] = wmma::__float_to_tf32(af.x[t]);
                #pragma unroll
                for (int n = 0; n < 4; n++) {
                    wmma::fragment<wmma::matrix_b, 16, 16, 8, wmma::precision::tf32,
                                   wmma::col_major> bf;
                    wmma::load_matrix_sync(bf, Kc + (n * 16) * LDP + kk, LDP);
                    #pragma unroll
                    for (int t = 0; t < bf.num_elements; t++)
                        bf.x[t] = wmma::__float_to_tf32(bf.x[t]);
                    wmma::mma_sync(sacc[n], af, bf, sacc[n]);
                }
            }

            // causal mask (register-side)
            const bool needmask = (64 * j + 63 > 128 * qt + warp_row0);
            if (needmask) {
                #pragma unroll
                for (int n = 0; n < 4; n++)
                    #pragma unroll
                    for (int t = 0; t < 8; t++) {
                        int c  = n * 16 + (lane & 3) * 2 + (t & 1) + ((t & 4) ? 8 : 0);
                        int lr = (t & 2) ? lr1 : lr0;
                        if (c + off > lr) sacc[n].x[t] = -1e30f;
                    }
            }

            // register online softmax
            float m0n = m0, m1n = m1;
            #pragma unroll
            for (int n = 0; n < 4; n++)
                #pragma unroll
                for (int t = 0; t < 8; t++) {
                    if (t & 2) m1n = fmaxf(m1n, sacc[n].x[t]);
                    else       m0n = fmaxf(m0n, sacc[n].x[t]);
                }
            m0n = fmaxf(m0n, __shfl_xor_sync(0xffffffffu, m0n, 1));
            m0n = fmaxf(m0n, __shfl_xor_sync(0xffffffffu, m0n, 2));
            m1n = fmaxf(m1n, __shfl_xor_sync(0xffffffffu, m1n, 1));
            m1n = fmaxf(m1n, __shfl_xor_sync(0xffffffffu, m1n, 2));

            const float al0 = __expf(m0 - m0n);
            const float al1 = __expf(m1 - m1n);

            float s0 = 0.f, s1 = 0.f;
            #pragma unroll
            for (int n = 0; n < 4; n++)
                #pragma unroll
                for (int t = 0; t < 8; t++) {
                    float p = __expf(sacc[n].x[t] - ((t & 2) ? m1n : m0n));
                    sacc[n].x[t] = p;
                    if (t & 2) s1 += p; else s0 += p;
                }
            s0 += __shfl_xor_sync(0xffffffffu, s0, 1);
            s0 += __shfl_xor_sync(0xffffffffu, s0, 2);
            s1 += __shfl_xor_sync(0xffffffffu, s1, 1);
            s1 += __shfl_xor_sync(0xffffffffu, s1, 2);

            m0 = m0n; m1 = m1n;
            l0 = l0 * al0 + s0;
            l1 = l1 * al1 + s1;

            // rescale O accumulators in registers
            #pragma unroll
            for (int n = 0; n < 4; n++)
                #pragma unroll
                for (int t = 0; t < 8; t++)
                    oacc[n].x[t] *= (t & 2) ? al1 : al0;

            // store P (only smem round trip)
            #pragma unroll
            for (int n = 0; n < 4; n++)
                wmma::store_matrix_sync(Ps + warp_row0 * LDP + n * 16, sacc[n],
                                        LDP, wmma::mem_row_major);
        }
        __syncthreads();  // S2: P visible (own rows only matter, but keeps KV reuse safe)

        if (active) {
            // O += P @ V
            #pragma unroll
            for (int kk = 0; kk < 64; kk += 8) {
                wmma::fragment<wmma::matrix_a, 16, 16, 8, wmma::precision::tf32,
                               wmma::row_major> af;
                wmma::load_matrix_sync(af, Ps + warp_row0 * LDP + kk, LDP);
                #pragma unroll
                for (int t = 0; t < af.num_elements; t++)
                    af.x[t] = wmma::__float_to_tf32(af.x[t]);
                #pragma unroll
                for (int n = 0; n < 4; n++) {
                    wmma::fragment<wmma::matrix_b, 16, 16, 8, wmma::precision::tf32,
                                   wmma::row_major> bf;
                    wmma::load_matrix_sync(bf, Vc + kk * LDP + n * 16, LDP);
                    #pragma unroll
                    for (int t = 0; t < bf.num_elements; t++)
                        bf.x[t] = wmma::__float_to_tf32(bf.x[t]);
                    wmma::mma_sync(oacc[n], af, bf, oacc[n]);
                }
            }
        }
        // loop: next S1 orders KV/Ps rewrites after these reads
    }

    // epilogue: O /= l, store direct to gmem (no smem, l in registers)
    const float rl0 = 1.f / l0;
    const float rl1 = 1.f / l1;
    float* ob = O + ((size_t)b * Sseq + (size_t)qt * 128 + warp_row0) * Eemb + h * Dd;
    #pragma unroll
    for (int n = 0; n < 4; n++) {
        #pragma unroll
        for (int t = 0; t < 8; t++)
            oacc[n].x[t] *= (t & 2) ? rl1 : rl0;
        wmma::store_matrix_sync(ob + n * 16, oacc[n], Eemb, wmma::mem_row_major);
    }
}

// ---------------------------------------------------------------------------
extern "C" void kernel_launch(void* const* d_in, const int* in_sizes, int n_in,
                              void* d_out, int out_size)
{
    const float* q   = (const float*)d_in[0];
    const float* k   = (const float*)d_in[1];
    const float* v   = (const float*)d_in[2];
    const float* w_q = (const float*)d_in[3];
    const float* b_q = (const float*)d_in[4];
    const float* w_k = (const float*)d_in[5];
    const float* b_k = (const float*)d_in[6];
    const float* w_v = (const float*)d_in[7];
    const float* b_v = (const float*)d_in[8];
    const float* w_o = (const float*)d_in[9];
    const float* b_o = (const float*)d_in[10];
    float* out = (float*)d_out;

    float *gq, *gk, *gv, *go;
    cudaGetSymbolAddress((void**)&gq, g_q);
    cudaGetSymbolAddress((void**)&gk, g_k);
    cudaGetSymbolAddress((void**)&gv, g_v);
    cudaGetSymbolAddress((void**)&go, g_o);

    cudaFuncSetAttribute(gemm_bias_kernel,
                         cudaFuncAttributeMaxDynamicSharedMemorySize,
                         GEMM_SMEM_BYTES);
    cudaFuncSetAttribute(flash_kernel,
                         cudaFuncAttributeMaxDynamicSharedMemorySize,
                         FLASH_SMEM_BYTES);

    dim3 gGrid(Eemb / 128, Mrows / 128);   // (8, 64)
    gemm_bias_kernel<<<gGrid, 256, GEMM_SMEM_BYTES>>>(q, w_q, b_q, gq);
    gemm_bias_kernel<<<gGrid, 256, GEMM_SMEM_BYTES>>>(k, w_k, b_k, gk);
    gemm_bias_kernel<<<gGrid, 256, GEMM_SMEM_BYTES>>>(v, w_v, b_v, gv);

    dim3 fGrid(Sseq / 128, Bb * Hh);       // (16, 64)
    flash_kernel<<<fGrid, 256, FLASH_SMEM_BYTES>>>(gq, gk, gv, go);

    gemm_bias_kernel<<<gGrid, 256, GEMM_SMEM_BYTES>>>(go, w_o, b_o, out);
}

// round 9
// speedup vs baseline: 1.6181x; 1.1343x over previous
#include <cuda_runtime.h>
#include <cuda_bf16.h>
#include <mma.h>
#include <cstdint>

using namespace nvcuda;

// Problem constants
static constexpr int Bb   = 4;
static constexpr int Sseq = 2048;
static constexpr int Eemb = 1024;
static constexpr int Hh   = 16;
static constexpr int Dd   = 64;
static constexpr int Mrows = Bb * Sseq;   // 8192

// Scratch (device globals: allocation-free)
__device__ float g_q[(size_t)Mrows * Eemb];
__device__ float g_k[(size_t)Mrows * Eemb];
__device__ float g_v[(size_t)Mrows * Eemb];
__device__ float g_o[(size_t)Mrows * Eemb];

// ---------------------------------------------------------------------------
// cp.async helpers
// ---------------------------------------------------------------------------
__device__ __forceinline__ void cp_async16(void* smem, const void* gmem) {
    uint32_t s = (uint32_t)__cvta_generic_to_shared(smem);
    asm volatile("cp.async.cg.shared.global [%0], [%1], 16;\n" :: "r"(s), "l"(gmem));
}
__device__ __forceinline__ void cp_commit() {
    asm volatile("cp.async.commit_group;\n");
}
template<int N> __device__ __forceinline__ void cp_wait() {
    asm volatile("cp.async.wait_group %0;\n" :: "n"(N));
}

// ---------------------------------------------------------------------------
// GEMM: C[M,N] = A[M,K] @ W[K,N] + bias[N]  (M=8192, K=N=1024), tf32 wmma
// 128x128x32 block tile, 4 warps of 64x64 (CUTLASS sm80 shape), 128 threads,
// cp.async double buffer, padded smem (LDA=36, LDB=132).
// 2 loads/mma (vs 3 with 32x64 warps), 16-deep mma ILP per k-step.
// ---------------------------------------------------------------------------
static constexpr int GBM = 128, GBN = 128, GBK = 32;
static constexpr int LDA = 36;    // GBK + 4
static constexpr int LDB = 132;   // GBN + 4
static constexpr int GEMM_SMEM_BYTES =
    (2 * GBM * LDA + 2 * GBK * LDB) * (int)sizeof(float);  // 70656

__global__ __launch_bounds__(128, 2) void gemm_bias_kernel(
    const float* __restrict__ A, const float* __restrict__ W,
    const float* __restrict__ bias, float* __restrict__ C)
{
    constexpr int K = 1024, N = 1024;

    extern __shared__ float smg[];
    float* As = smg;                   // [2][GBM*LDA]
    float* Bs = smg + 2 * GBM * LDA;   // [2][GBK*LDB]

    const int tid  = threadIdx.x;
    const int lane = tid & 31;
    const int bm   = blockIdx.y * GBM;
    const int bn   = blockIdx.x * GBN;
    const int warp = tid >> 5;         // 0..3
    const int wr   = (warp >> 1) * 64; // row offset
    const int wc   = (warp & 1) * 64;  // col offset

    auto issue_tile = [&](int kt, int buf) {
        const int k0 = kt * GBK;
        float* Ab = As + buf * GBM * LDA;
        float* Bbuf = Bs + buf * GBK * LDB;
        #pragma unroll
        for (int t = 0; t < 8; t++) {
            int lin = tid + t * 128;
            int r = lin >> 3, c4 = lin & 7;
            cp_async16(Ab + r * LDA + c4 * 4,
                       A + (size_t)(bm + r) * K + k0 + c4 * 4);
        }
        #pragma unroll
        for (int t = 0; t < 8; t++) {
            int lin = tid + t * 128;
            int r = lin >> 5, c4 = lin & 31;
            cp_async16(Bbuf + r * LDB + c4 * 4,
                       W + (size_t)(k0 + r) * N + bn + c4 * 4);
        }
    };

    issue_tile(0, 0);
    cp_commit();

    wmma::fragment<wmma::accumulator, 16, 16, 8, float> acc[4][4];
    #pragma unroll
    for (int i = 0; i < 4; i++)
        #pragma unroll
        for (int j = 0; j < 4; j++)
            wmma::fill_fragment(acc[i][j], 0.f);

    const int KT = K / GBK;  // 32
    for (int kt = 0; kt < KT; kt++) {
        const int cur = kt & 1;
        cp_wait<0>();
        __syncthreads();
        if (kt + 1 < KT) {
            issue_tile(kt + 1, cur ^ 1);
            cp_commit();
        }

        const float* Ab = As + cur * GBM * LDA;
        const float* Bbuf = Bs + cur * GBK * LDB;

        #pragma unroll
        for (int kk = 0; kk < GBK; kk += 8) {
            wmma::fragment<wmma::matrix_a, 16, 16, 8, wmma::precision::tf32,
                           wmma::row_major> af[4];
            #pragma unroll
            for (int i = 0; i < 4; i++) {
                wmma::load_matrix_sync(af[i], Ab + (wr + i * 16) * LDA + kk, LDA);
                #pragma unroll
                for (int t = 0; t < af[i].num_elements; t++)
                    af[i].x[t] = wmma::__float_to_tf32(af[i].x[t]);
            }
            #pragma unroll
            for (int j = 0; j < 4; j++) {
                wmma::fragment<wmma::matrix_b, 16, 16, 8, wmma::precision::tf32,
                               wmma::row_major> bf;
                wmma::load_matrix_sync(bf, Bbuf + kk * LDB + wc + j * 16, LDB);
                #pragma unroll
                for (int t = 0; t < bf.num_elements; t++)
                    bf.x[t] = wmma::__float_to_tf32(bf.x[t]);
                #pragma unroll
                for (int i = 0; i < 4; i++)
                    wmma::mma_sync(acc[i][j], af[i], bf, acc[i][j]);
            }
        }
    }

    // epilogue: add bias per element (standard m16n8 acc layout cols), store
    #pragma unroll
    for (int j = 0; j < 4; j++) {
        const int col0 = bn + wc + j * 16 + (lane & 3) * 2;
        float b0 = __ldg(bias + col0);
        float b1 = __ldg(bias + col0 + 1);
        float b8 = __ldg(bias + col0 + 8);
        float b9 = __ldg(bias + col0 + 9);
        #pragma unroll
        for (int i = 0; i < 4; i++) {
            acc[i][j].x[0] += b0; acc[i][j].x[1] += b1;
            acc[i][j].x[2] += b0; acc[i][j].x[3] += b1;
            acc[i][j].x[4] += b8; acc[i][j].x[5] += b9;
            acc[i][j].x[6] += b8; acc[i][j].x[7] += b9;
            wmma::store_matrix_sync(
                C + (size_t)(bm + wr + i * 16) * N + col0 - (lane & 3) * 2,
                acc[i][j], N, wmma::mem_row_major);
        }
    }
}

// ---------------------------------------------------------------------------
// Causal flash attention, tf32 wmma, Br=128, Bc=64, 8 warps,
// 3-stage cp.async KV ring (prefetch 2 tiles ahead).
// Warp w owns rows [16w,16w+16); softmax fully in registers; P through smem
// once as the PV A-operand. smem = 174 KB -> 1 CTA/SM.
// ---------------------------------------------------------------------------
static constexpr int LDP = 68;
static constexpr int KVTILE = 64 * LDP;        // 64x68
static constexpr int QTILE  = 128 * LDP;       // 128x68
static constexpr int FLASH_SMEM_BYTES =
    (QTILE + 6 * KVTILE + QTILE) * (int)sizeof(float);   // 174080

__global__ __launch_bounds__(256, 1) void flash_kernel(
    const float* __restrict__ Q, const float* __restrict__ Kg,
    const float* __restrict__ V, float* __restrict__ O)
{
    extern __shared__ float sm[];
    float* Qs = sm;                    // 128x68
    float* Ks = Qs + QTILE;            // [3] 64x68
    float* Vs = Ks + 3 * KVTILE;       // [3] 64x68
    float* Ps = Vs + 3 * KVTILE;       // 128x68

    const int tid  = threadIdx.x;
    const int warp = tid >> 5;         // 0..7 -> rows 16w..16w+15
    const int lane = tid & 31;
    const int qt   = (Sseq / 128 - 1) - blockIdx.x;  // heavy tiles first
    const int bh   = blockIdx.y;
    const int b    = bh >> 4;
    const int h    = bh & 15;
    const float scale = 0.125f;        // 1/sqrt(64)

    const float* qb = Q + ((size_t)b * Sseq + (size_t)qt * 128) * Eemb + h * Dd;
    const float* kb = Kg + (size_t)b * Sseq * Eemb + h * Dd;
    const float* vb = V + (size_t)b * Sseq * Eemb + h * Dd;

    auto issueKV = [&](int j, int buf) {
        const float* kt = kb + (size_t)j * 64 * Eemb;
        const float* vt = vb + (size_t)j * 64 * Eemb;
        float* Kd = Ks + buf * KVTILE;
        float* Vd = Vs + buf * KVTILE;
        #pragma unroll
        for (int t = 0; t < 4; t++) {
            int lin = tid + t * 256;
            int r = lin >> 4, c4 = lin & 15;
            cp_async16(Kd + r * LDP + c4 * 4, kt + (size_t)r * Eemb + c4 * 4);
            cp_async16(Vd + r * LDP + c4 * 4, vt + (size_t)r * Eemb + c4 * 4);
        }
    };

    const int nkv = 2 * qt + 2;  // KV 64-row tiles covering keys <= last row

    issueKV(0, 0);
    cp_commit();
    if (nkv > 1) { issueKV(1, 1); cp_commit(); }

    // Q tile (128 rows), pre-scaled
    #pragma unroll
    for (int t = 0; t < 8; t++) {
        int lin = tid + t * 256;
        int r = lin >> 4, c4 = lin & 15;
        float4 v4 = *(const float4*)(qb + (size_t)r * Eemb + c4 * 4);
        v4.x *= scale; v4.y *= scale; v4.z *= scale; v4.w *= scale;
        *(float4*)(Qs + r * LDP + c4 * 4) = v4;
    }

    // register stats for this thread's two rows (lane>>2, lane>>2+8)
    float m0 = -1e30f, m1 = -1e30f, l0 = 0.f, l1 = 0.f;

    wmma::fragment<wmma::accumulator, 16, 16, 8, float> oacc[4];
    #pragma unroll
    for (int n = 0; n < 4; n++) wmma::fill_fragment(oacc[n], 0.f);

    const int warp_row0 = warp * 16;            // local row base
    const int lr0 = warp_row0 + (lane >> 2);    // this thread's local rows
    const int lr1 = lr0 + 8;

    int cur = 0;
    for (int j = 0; j < nkv; j++) {
        // wait for tile j (keep at most the newest group in flight)
        if (j + 1 < nkv) cp_wait<1>(); else cp_wait<0>();
        __syncthreads();  // S1: KV[cur] visible; buffer (cur+2)%3 free
        if (j + 2 < nkv) {
            int nb = cur + 2; if (nb >= 3) nb -= 3;
            issueKV(j + 2, nb);
            cp_commit();
        }

        const float* Kc = Ks + cur * KVTILE;
        const float* Vc = Vs + cur * KVTILE;

        const int off = 64 * j - 128 * qt;        // col+off > lr  => masked
        const bool active = (64 * j <= 128 * qt + warp_row0 + 15);

        if (active) {
            // S = Q @ K^T (16x64 per warp)
            wmma::fragment<wmma::accumulator, 16, 16, 8, float> sacc[4];
            #pragma unroll
            for (int n = 0; n < 4; n++) wmma::fill_fragment(sacc[n], 0.f);
            #pragma unroll
            for (int kk = 0; kk < 64; kk += 8) {
                wmma::fragment<wmma::matrix_a, 16, 16, 8, wmma::precision::tf32,
                               wmma::row_major> af;
                wmma::load_matrix_sync(af, Qs + warp_row0 * LDP + kk, LDP);
                #pragma unroll
                for (int t = 0; t < af.num_elements; t++)
                    af.x[t] = wmma::__float_to_tf32(af.x[t]);
                #pragma unroll
                for (int n = 0; n < 4; n++) {
                    wmma::fragment<wmma::matrix_b, 16, 16, 8, wmma::precision::tf32,
                                   wmma::col_major> bf;
                    wmma::load_matrix_sync(bf, Kc + (n * 16) * LDP + kk, LDP);
                    #pragma unroll
                    for (int t = 0; t < bf.num_elements; t++)
                        bf.x[t] = wmma::__float_to_tf32(bf.x[t]);
                    wmma::mma_sync(sacc[n], af, bf, sacc[n]);
                }
            }

            // causal mask (register-side)
            const bool needmask = (64 * j + 63 > 128 * qt + warp_row0);
            if (needmask) {
                #pragma unroll
                for (int n = 0; n < 4; n++)
                    #pragma unroll
                    for (int t = 0; t < 8; t++) {
                        int c  = n * 16 + (lane & 3) * 2 + (t & 1) + ((t & 4) ? 8 : 0);
                        int lr = (t & 2) ? lr1 : lr0;
                        if (c + off > lr) sacc[n].x[t] = -1e30f;
                    }
            }

            // register online softmax
            float m0n = m0, m1n = m1;
            #pragma unroll
            for (int n = 0; n < 4; n++)
                #pragma unroll
                for (int t = 0; t < 8; t++) {
                    if (t & 2) m1n = fmaxf(m1n, sacc[n].x[t]);
                    else       m0n = fmaxf(m0n, sacc[n].x[t]);
                }
            m0n = fmaxf(m0n, __shfl_xor_sync(0xffffffffu, m0n, 1));
            m0n = fmaxf(m0n, __shfl_xor_sync(0xffffffffu, m0n, 2));
            m1n = fmaxf(m1n, __shfl_xor_sync(0xffffffffu, m1n, 1));
            m1n = fmaxf(m1n, __shfl_xor_sync(0xffffffffu, m1n, 2));

            const float al0 = __expf(m0 - m0n);
            const float al1 = __expf(m1 - m1n);

            float s0 = 0.f, s1 = 0.f;
            #pragma unroll
            for (int n = 0; n < 4; n++)
                #pragma unroll
                for (int t = 0; t < 8; t++) {
                    float p = __expf(sacc[n].x[t] - ((t & 2) ? m1n : m0n));
                    sacc[n].x[t] = p;
                    if (t & 2) s1 += p; else s0 += p;
                }
            s0 += __shfl_xor_sync(0xffffffffu, s0, 1);
            s0 += __shfl_xor_sync(0xffffffffu, s0, 2);
            s1 += __shfl_xor_sync(0xffffffffu, s1, 1);
            s1 += __shfl_xor_sync(0xffffffffu, s1, 2);

            m0 = m0n; m1 = m1n;
            l0 = l0 * al0 + s0;
            l1 = l1 * al1 + s1;

            // rescale O accumulators in registers
            #pragma unroll
            for (int n = 0; n < 4; n++)
                #pragma unroll
                for (int t = 0; t < 8; t++)
                    oacc[n].x[t] *= (t & 2) ? al1 : al0;

            // store P (only smem round trip)
            #pragma unroll
            for (int n = 0; n < 4; n++)
                wmma::store_matrix_sync(Ps + warp_row0 * LDP + n * 16, sacc[n],
                                        LDP, wmma::mem_row_major);
        }
        __syncthreads();  // S2

        if (active) {
            // O += P @ V
            #pragma unroll
            for (int kk = 0; kk < 64; kk += 8) {
                wmma::fragment<wmma::matrix_a, 16, 16, 8, wmma::precision::tf32,
                               wmma::row_major> af;
                wmma::load_matrix_sync(af, Ps + warp_row0 * LDP + kk, LDP);
                #pragma unroll
                for (int t = 0; t < af.num_elements; t++)
                    af.x[t] = wmma::__float_to_tf32(af.x[t]);
                #pragma unroll
                for (int n = 0; n < 4; n++) {
                    wmma::fragment<wmma::matrix_b, 16, 16, 8, wmma::precision::tf32,
                                   wmma::row_major> bf;
                    wmma::load_matrix_sync(bf, Vc + kk * LDP + n * 16, LDP);
                    #pragma unroll
                    for (int t = 0; t < bf.num_elements; t++)
                        bf.x[t] = wmma::__float_to_tf32(bf.x[t]);
                    wmma::mma_sync(oacc[n], af, bf, oacc[n]);
                }
            }
        }
        cur++; if (cur == 3) cur = 0;
        // loop: next S1 orders KV/Ps rewrites after these reads
    }

    // epilogue: O /= l, store direct to gmem (no smem, l in registers)
    const float rl0 = 1.f / l0;
    const float rl1 = 1.f / l1;
    float* ob = O + ((size_t)b * Sseq + (size_t)qt * 128 + warp_row0) * Eemb + h * Dd;
    #pragma unroll
    for (int n = 0; n < 4; n++) {
        #pragma unroll
        for (int t = 0; t < 8; t++)
            oacc[n].x[t] *= (t & 2) ? rl1 : rl0;
        wmma::store_matrix_sync(ob + n * 16, oacc[n], Eemb, wmma::mem_row_major);
    }
}

// ---------------------------------------------------------------------------
extern "C" void kernel_launch(void* const* d_in, const int* in_sizes, int n_in,
                              void* d_out, int out_size)
{
    const float* q   = (const float*)d_in[0];
    const float* k   = (const float*)d_in[1];
    const float* v   = (const float*)d_in[2];
    const float* w_q = (const float*)d_in[3];
    const float* b_q = (const float*)d_in[4];
    const float* w_k = (const float*)d_in[5];
    const float* b_k = (const float*)d_in[6];
    const float* w_v = (const float*)d_in[7];
    const float* b_v = (const float*)d_in[8];
    const float* w_o = (const float*)d_in[9];
    const float* b_o = (const float*)d_in[10];
    float* out = (float*)d_out;

    float *gq, *gk, *gv, *go;
    cudaGetSymbolAddress((void**)&gq, g_q);
    cudaGetSymbolAddress((void**)&gk, g_k);
    cudaGetSymbolAddress((void**)&gv, g_v);
    cudaGetSymbolAddress((void**)&go, g_o);

    cudaFuncSetAttribute(gemm_bias_kernel,
                         cudaFuncAttributeMaxDynamicSharedMemorySize,
                         GEMM_SMEM_BYTES);
    cudaFuncSetAttribute(flash_kernel,
                         cudaFuncAttributeMaxDynamicSharedMemorySize,
                         FLASH_SMEM_BYTES);

    dim3 gGrid(Eemb / 128, Mrows / 128);   // (8, 64)
    gemm_bias_kernel<<<gGrid, 128, GEMM_SMEM_BYTES>>>(q, w_q, b_q, gq);
    gemm_bias_kernel<<<gGrid, 128, GEMM_SMEM_BYTES>>>(k, w_k, b_k, gk);
    gemm_bias_kernel<<<gGrid, 128, GEMM_SMEM_BYTES>>>(v, w_v, b_v, gv);

    dim3 fGrid(Sseq / 128, Bb * Hh);       // (16, 64)
    flash_kernel<<<fGrid, 256, FLASH_SMEM_BYTES>>>(gq, gk, gv, go);

    gemm_bias_kernel<<<gGrid, 128, GEMM_SMEM_BYTES>>>(go, w_o, b_o, out);
}

// round 10
// speedup vs baseline: 1.6563x; 1.0236x over previous
#include <cuda_runtime.h>
#include <cuda_bf16.h>
#include <mma.h>
#include <cstdint>

using namespace nvcuda;

// Problem constants
static constexpr int Bb   = 4;
static constexpr int Sseq = 2048;
static constexpr int Eemb = 1024;
static constexpr int Hh   = 16;
static constexpr int Dd   = 64;
static constexpr int Mrows = Bb * Sseq;   // 8192

// Scratch (device globals: allocation-free)
__device__ float g_q[(size_t)Mrows * Eemb];
__device__ float g_k[(size_t)Mrows * Eemb];
__device__ float g_v[(size_t)Mrows * Eemb];
__device__ float g_o[(size_t)Mrows * Eemb];

// ---------------------------------------------------------------------------
// cp.async helpers
// ---------------------------------------------------------------------------
__device__ __forceinline__ void cp_async16(void* smem, const void* gmem) {
    uint32_t s = (uint32_t)__cvta_generic_to_shared(smem);
    asm volatile("cp.async.cg.shared.global [%0], [%1], 16;\n" :: "r"(s), "l"(gmem));
}
__device__ __forceinline__ void cp_commit() {
    asm volatile("cp.async.commit_group;\n");
}
template<int N> __device__ __forceinline__ void cp_wait() {
    asm volatile("cp.async.wait_group %0;\n" :: "n"(N));
}

// ---------------------------------------------------------------------------
// GEMM: C[M,N] = A[M,K] @ W[K,N] + bias[N]  (M=8192, K=N=1024), tf32 wmma
// 128x128x32 block tile, 4 warps of 64x64, 128 threads, cp.async double
// buffer, padded smem (LDA=36, LDB=132). Unchanged from round 9 (behaved
// as predicted: ~263 us each).
// ---------------------------------------------------------------------------
static constexpr int GBM = 128, GBN = 128, GBK = 32;
static constexpr int LDA = 36;    // GBK + 4
static constexpr int LDB = 132;   // GBN + 4
static constexpr int GEMM_SMEM_BYTES =
    (2 * GBM * LDA + 2 * GBK * LDB) * (int)sizeof(float);  // 70656

__global__ __launch_bounds__(128, 2) void gemm_bias_kernel(
    const float* __restrict__ A, const float* __restrict__ W,
    const float* __restrict__ bias, float* __restrict__ C)
{
    constexpr int K = 1024, N = 1024;

    extern __shared__ float smg[];
    float* As = smg;                   // [2][GBM*LDA]
    float* Bs = smg + 2 * GBM * LDA;   // [2][GBK*LDB]

    const int tid  = threadIdx.x;
    const int lane = tid & 31;
    const int bm   = blockIdx.y * GBM;
    const int bn   = blockIdx.x * GBN;
    const int warp = tid >> 5;         // 0..3
    const int wr   = (warp >> 1) * 64; // row offset
    const int wc   = (warp & 1) * 64;  // col offset

    auto issue_tile = [&](int kt, int buf) {
        const int k0 = kt * GBK;
        float* Ab = As + buf * GBM * LDA;
        float* Bbuf = Bs + buf * GBK * LDB;
        #pragma unroll
        for (int t = 0; t < 8; t++) {
            int lin = tid + t * 128;
            int r = lin >> 3, c4 = lin & 7;
            cp_async16(Ab + r * LDA + c4 * 4,
                       A + (size_t)(bm + r) * K + k0 + c4 * 4);
        }
        #pragma unroll
        for (int t = 0; t < 8; t++) {
            int lin = tid + t * 128;
            int r = lin >> 5, c4 = lin & 31;
            cp_async16(Bbuf + r * LDB + c4 * 4,
                       W + (size_t)(k0 + r) * N + bn + c4 * 4);
        }
    };

    issue_tile(0, 0);
    cp_commit();

    wmma::fragment<wmma::accumulator, 16, 16, 8, float> acc[4][4];
    #pragma unroll
    for (int i = 0; i < 4; i++)
        #pragma unroll
        for (int j = 0; j < 4; j++)
            wmma::fill_fragment(acc[i][j], 0.f);

    const int KT = K / GBK;  // 32
    for (int kt = 0; kt < KT; kt++) {
        const int cur = kt & 1;
        cp_wait<0>();
        __syncthreads();
        if (kt + 1 < KT) {
            issue_tile(kt + 1, cur ^ 1);
            cp_commit();
        }

        const float* Ab = As + cur * GBM * LDA;
        const float* Bbuf = Bs + cur * GBK * LDB;

        #pragma unroll
        for (int kk = 0; kk < GBK; kk += 8) {
            wmma::fragment<wmma::matrix_a, 16, 16, 8, wmma::precision::tf32,
                           wmma::row_major> af[4];
            #pragma unroll
            for (int i = 0; i < 4; i++) {
                wmma::load_matrix_sync(af[i], Ab + (wr + i * 16) * LDA + kk, LDA);
                #pragma unroll
                for (int t = 0; t < af[i].num_elements; t++)
                    af[i].x[t] = wmma::__float_to_tf32(af[i].x[t]);
            }
            #pragma unroll
            for (int j = 0; j < 4; j++) {
                wmma::fragment<wmma::matrix_b, 16, 16, 8, wmma::precision::tf32,
                               wmma::row_major> bf;
                wmma::load_matrix_sync(bf, Bbuf + kk * LDB + wc + j * 16, LDB);
                #pragma unroll
                for (int t = 0; t < bf.num_elements; t++)
                    bf.x[t] = wmma::__float_to_tf32(bf.x[t]);
                #pragma unroll
                for (int i = 0; i < 4; i++)
                    wmma::mma_sync(acc[i][j], af[i], bf, acc[i][j]);
            }
        }
    }

    // epilogue: add bias per element (standard m16n8 acc layout cols), store
    #pragma unroll
    for (int j = 0; j < 4; j++) {
        const int col0 = bn + wc + j * 16 + (lane & 3) * 2;
        float b0 = __ldg(bias + col0);
        float b1 = __ldg(bias + col0 + 1);
        float b8 = __ldg(bias + col0 + 8);
        float b9 = __ldg(bias + col0 + 9);
        #pragma unroll
        for (int i = 0; i < 4; i++) {
            acc[i][j].x[0] += b0; acc[i][j].x[1] += b1;
            acc[i][j].x[2] += b0; acc[i][j].x[3] += b1;
            acc[i][j].x[4] += b8; acc[i][j].x[5] += b9;
            acc[i][j].x[6] += b8; acc[i][j].x[7] += b9;
            wmma::store_matrix_sync(
                C + (size_t)(bm + wr + i * 16) * N + col0 - (lane & 3) * 2,
                acc[i][j], N, wmma::mem_row_major);
        }
    }
}

// ---------------------------------------------------------------------------
// Causal flash attention, tf32 wmma, Br=64, Bc=64, 4 warps (128 threads),
// double-buffered KV, register softmax, P through smem once.
// Per-warp work identical to the Br=128 version (16 rows x 64 cols), but
// 128 threads x ~250 regs = 32K regs and 104 KB smem -> 2 independent
// CTAs/SM: one CTA's softmax overlaps the other's mma.
// ---------------------------------------------------------------------------
static constexpr int LDP = 68;
static constexpr int KVTILE = 64 * LDP;        // 64x68
static constexpr int FLASH_SMEM_BYTES =
    (6 * KVTILE) * (int)sizeof(float);         // Q + 2K + 2V + P = 104448

__global__ __launch_bounds__(128, 2) void flash_kernel(
    const float* __restrict__ Q, const float* __restrict__ Kg,
    const float* __restrict__ V, float* __restrict__ O)
{
    extern __shared__ float sm[];
    float* Qs = sm;                    // 64x68
    float* Ks = Qs + KVTILE;           // [2] 64x68
    float* Vs = Ks + 2 * KVTILE;       // [2] 64x68
    float* Ps = Vs + 2 * KVTILE;       // 64x68

    const int tid  = threadIdx.x;
    const int warp = tid >> 5;         // 0..3 -> rows 16w..16w+15
    const int lane = tid & 31;
    const int qt   = (Sseq / 64 - 1) - blockIdx.x;   // heavy tiles first
    const int bh   = blockIdx.y;
    const int b    = bh >> 4;
    const int h    = bh & 15;
    const float scale = 0.125f;        // 1/sqrt(64)

    const float* qb = Q + ((size_t)b * Sseq + (size_t)qt * 64) * Eemb + h * Dd;
    const float* kb = Kg + (size_t)b * Sseq * Eemb + h * Dd;
    const float* vb = V + (size_t)b * Sseq * Eemb + h * Dd;

    auto issueKV = [&](int j, int buf) {
        const float* kt = kb + (size_t)j * 64 * Eemb;
        const float* vt = vb + (size_t)j * 64 * Eemb;
        float* Kd = Ks + buf * KVTILE;
        float* Vd = Vs + buf * KVTILE;
        #pragma unroll
        for (int t = 0; t < 8; t++) {
            int lin = tid + t * 128;
            int r = lin >> 4, c4 = lin & 15;
            cp_async16(Kd + r * LDP + c4 * 4, kt + (size_t)r * Eemb + c4 * 4);
            cp_async16(Vd + r * LDP + c4 * 4, vt + (size_t)r * Eemb + c4 * 4);
        }
    };

    issueKV(0, 0);
    cp_commit();

    // Q tile (64 rows), pre-scaled
    #pragma unroll
    for (int t = 0; t < 8; t++) {
        int lin = tid + t * 128;
        int r = lin >> 4, c4 = lin & 15;
        float4 v4 = *(const float4*)(qb + (size_t)r * Eemb + c4 * 4);
        v4.x *= scale; v4.y *= scale; v4.z *= scale; v4.w *= scale;
        *(float4*)(Qs + r * LDP + c4 * 4) = v4;
    }

    // register stats for this thread's two rows (lane>>2, lane>>2+8)
    float m0 = -1e30f, m1 = -1e30f, l0 = 0.f, l1 = 0.f;

    wmma::fragment<wmma::accumulator, 16, 16, 8, float> oacc[4];
    #pragma unroll
    for (int n = 0; n < 4; n++) wmma::fill_fragment(oacc[n], 0.f);

    const int warp_row0 = warp * 16;            // local row base
    const int lr0 = warp_row0 + (lane >> 2);    // this thread's local rows
    const int lr1 = lr0 + 8;
    const int nkv = qt + 1;                     // 64-key tiles

    for (int j = 0; j < nkv; j++) {
        const int cur = j & 1;

        cp_wait<0>();
        __syncthreads();  // S1: KV[cur] visible; every warp finished iter j-1
        if (j + 1 < nkv) {
            issueKV(j + 1, cur ^ 1);
            cp_commit();
        }

        const float* Kc = Ks + cur * KVTILE;
        const float* Vc = Vs + cur * KVTILE;

        // S = Q @ K^T (16x64 per warp)
        wmma::fragment<wmma::accumulator, 16, 16, 8, float> sacc[4];
        #pragma unroll
        for (int n = 0; n < 4; n++) wmma::fill_fragment(sacc[n], 0.f);
        #pragma unroll
        for (int kk = 0; kk < 64; kk += 8) {
            wmma::fragment<wmma::matrix_a, 16, 16, 8, wmma::precision::tf32,
                           wmma::row_major> af;
            wmma::load_matrix_sync(af, Qs + warp_row0 * LDP + kk, LDP);
            #pragma unroll
            for (int t = 0; t < af.num_elements; t++)
                af.x[t] = wmma::__float_to_tf32(af.x[t]);
            #pragma unroll
            for (int n = 0; n < 4; n++) {
                wmma::fragment<wmma::matrix_b, 16, 16, 8, wmma::precision::tf32,
                               wmma::col_major> bf;
                wmma::load_matrix_sync(bf, Kc + (n * 16) * LDP + kk, LDP);
                #pragma unroll
                for (int t = 0; t < bf.num_elements; t++)
                    bf.x[t] = wmma::__float_to_tf32(bf.x[t]);
                wmma::mma_sync(sacc[n], af, bf, sacc[n]);
            }
        }

        // causal mask (only the diagonal tile needs it)
        if (j == qt) {
            #pragma unroll
            for (int n = 0; n < 4; n++)
                #pragma unroll
                for (int t = 0; t < 8; t++) {
                    int c  = n * 16 + (lane & 3) * 2 + (t & 1) + ((t & 4) ? 8 : 0);
                    int lr = (t & 2) ? lr1 : lr0;
                    if (c > lr) sacc[n].x[t] = -1e30f;
                }
        }

        // register online softmax
        float m0n = m0, m1n = m1;
        #pragma unroll
        for (int n = 0; n < 4; n++)
            #pragma unroll
            for (int t = 0; t < 8; t++) {
                if (t & 2) m1n = fmaxf(m1n, sacc[n].x[t]);
                else       m0n = fmaxf(m0n, sacc[n].x[t]);
            }
        m0n = fmaxf(m0n, __shfl_xor_sync(0xffffffffu, m0n, 1));
        m0n = fmaxf(m0n, __shfl_xor_sync(0xffffffffu, m0n, 2));
        m1n = fmaxf(m1n, __shfl_xor_sync(0xffffffffu, m1n, 1));
        m1n = fmaxf(m1n, __shfl_xor_sync(0xffffffffu, m1n, 2));

        const float al0 = __expf(m0 - m0n);
        const float al1 = __expf(m1 - m1n);

        float s0 = 0.f, s1 = 0.f;
        #pragma unroll
        for (int n = 0; n < 4; n++)
            #pragma unroll
            for (int t = 0; t < 8; t++) {
                float p = __expf(sacc[n].x[t] - ((t & 2) ? m1n : m0n));
                sacc[n].x[t] = p;
                if (t & 2) s1 += p; else s0 += p;
            }
        s0 += __shfl_xor_sync(0xffffffffu, s0, 1);
        s0 += __shfl_xor_sync(0xffffffffu, s0, 2);
        s1 += __shfl_xor_sync(0xffffffffu, s1, 1);
        s1 += __shfl_xor_sync(0xffffffffu, s1, 2);

        m0 = m0n; m1 = m1n;
        l0 = l0 * al0 + s0;
        l1 = l1 * al1 + s1;

        // rescale O accumulators in registers
        #pragma unroll
        for (int n = 0; n < 4; n++)
            #pragma unroll
            for (int t = 0; t < 8; t++)
                oacc[n].x[t] *= (t & 2) ? al1 : al0;

        // store P (only smem round trip)
        #pragma unroll
        for (int n = 0; n < 4; n++)
            wmma::store_matrix_sync(Ps + warp_row0 * LDP + n * 16, sacc[n],
                                    LDP, wmma::mem_row_major);
        __syncthreads();  // S2: P visible

        // O += P @ V
        #pragma unroll
        for (int kk = 0; kk < 64; kk += 8) {
            wmma::fragment<wmma::matrix_a, 16, 16, 8, wmma::precision::tf32,
                           wmma::row_major> af;
            wmma::load_matrix_sync(af, Ps + warp_row0 * LDP + kk, LDP);
            #pragma unroll
            for (int t = 0; t < af.num_elements; t++)
                af.x[t] = wmma::__float_to_tf32(af.x[t]);
            #pragma unroll
            for (int n = 0; n < 4; n++) {
                wmma::fragment<wmma::matrix_b, 16, 16, 8, wmma::precision::tf32,
                               wmma::row_major> bf;
                wmma::load_matrix_sync(bf, Vc + kk * LDP + n * 16, LDP);
                #pragma unroll
                for (int t = 0; t < bf.num_elements; t++)
                    bf.x[t] = wmma::__float_to_tf32(bf.x[t]);
                wmma::mma_sync(oacc[n], af, bf, oacc[n]);
            }
        }
        // loop: next S1 orders KV/Ps rewrites after these reads
    }

    // epilogue: O /= l, store direct to gmem
    const float rl0 = 1.f / l0;
    const float rl1 = 1.f / l1;
    float* ob = O + ((size_t)b * Sseq + (size_t)qt * 64 + warp_row0) * Eemb + h * Dd;
    #pragma unroll
    for (int n = 0; n < 4; n++) {
        #pragma unroll
        for (int t = 0; t < 8; t++)
            oacc[n].x[t] *= (t & 2) ? rl1 : rl0;
        wmma::store_matrix_sync(ob + n * 16, oacc[n], Eemb, wmma::mem_row_major);
    }
}

// ---------------------------------------------------------------------------
extern "C" void kernel_launch(void* const* d_in, const int* in_sizes, int n_in,
                              void* d_out, int out_size)
{
    const float* q   = (const float*)d_in[0];
    const float* k   = (const float*)d_in[1];
    const float* v   = (const float*)d_in[2];
    const float* w_q = (const float*)d_in[3];
    const float* b_q = (const float*)d_in[4];
    const float* w_k = (const float*)d_in[5];
    const float* b_k = (const float*)d_in[6];
    const float* w_v = (const float*)d_in[7];
    const float* b_v = (const float*)d_in[8];
    const float* w_o = (const float*)d_in[9];
    const float* b_o = (const float*)d_in[10];
    float* out = (float*)d_out;

    float *gq, *gk, *gv, *go;
    cudaGetSymbolAddress((void**)&gq, g_q);
    cudaGetSymbolAddress((void**)&gk, g_k);
    cudaGetSymbolAddress((void**)&gv, g_v);
    cudaGetSymbolAddress((void**)&go, g_o);

    cudaFuncSetAttribute(gemm_bias_kernel,
                         cudaFuncAttributeMaxDynamicSharedMemorySize,
                         GEMM_SMEM_BYTES);
    cudaFuncSetAttribute(flash_kernel,
                         cudaFuncAttributeMaxDynamicSharedMemorySize,
                         FLASH_SMEM_BYTES);

    dim3 gGrid(Eemb / 128, Mrows / 128);   // (8, 64)
    gemm_bias_kernel<<<gGrid, 128, GEMM_SMEM_BYTES>>>(q, w_q, b_q, gq);
    gemm_bias_kernel<<<gGrid, 128, GEMM_SMEM_BYTES>>>(k, w_k, b_k, gk);
    gemm_bias_kernel<<<gGrid, 128, GEMM_SMEM_BYTES>>>(v, w_v, b_v, gv);

    dim3 fGrid(Sseq / 64, Bb * Hh);        // (32, 64)
    flash_kernel<<<fGrid, 128, FLASH_SMEM_BYTES>>>(gq, gk, gv, go);

    gemm_bias_kernel<<<gGrid, 128, GEMM_SMEM_BYTES>>>(go, w_o, b_o, out);
}